// round 2
// baseline (speedup 1.0000x reference)
#include <cuda_runtime.h>

// SPU transformer bound propagation: elementwise over N=8192 rows.
// 2 rows per thread via float4; 128 blocks x 32 threads = one warp per SM
// across 128 SMs -> minimal exposed latency, zero per-SM queue contention.

__device__ __forceinline__ float spu_f(float x) {
    // Branchless: compute both arms, select.
    // x >= 0 : x*x - 0.5
    // x <  0 : 1/(1 + exp(x)) - 1   (exp(x) < 1 for x<0; safe for all finite x here)
    float pos = fmaf(x, x, -0.5f);
    float neg = 1.0f / (1.0f + expf(x)) - 1.0f;
    return (x >= 0.0f) ? pos : neg;
}

__device__ __forceinline__ float2 spu_row(float2 b, float2 ls, float2 lsh, float2 lb2) {
    float l = b.x, u = b.y;
    float vl = spu_f(l);
    float vu = spu_f(u);

    bool neg   = (u <= 0.0f);
    bool pos   = (l >= 0.0f);
    bool cross = !(neg || pos);

    float all_slopes = (vu - vl) / (u - l);
    float slope_u = (pos || cross) ? all_slopes : 0.0f;
    float slope_l = neg ? all_slopes : 0.0f;

    bool sw = (all_slopes < 0.0f);
    float v_l = sw ? vu : vl;
    float v_u = sw ? vl : vu;
    float b_l = sw ? u : l;
    float b_u = sw ? l : u;

    float bnd_l = cross ? -0.5f : v_l;
    float bnd_u = v_u;

    float shift_u = v_u - slope_u * b_u;
    float shift_l = cross ? -0.5f : (v_l - slope_l * b_l);

    float Ud = slope_u * ls.y;
    float UV = fmaf(slope_u, lsh.y, shift_u);
    float Ld = slope_l * ls.x;
    float LV = fmaf(slope_l, lsh.x, shift_l);

    float lb = fmaxf(Ld, 0.0f) * lb2.x + fminf(Ld, 0.0f) * lb2.y + LV;
    float ub = fmaxf(Ud, 0.0f) * lb2.y + fminf(Ud, 0.0f) * lb2.x + UV;

    float out_l = (lb > bnd_l) ? lb : bnd_l;
    float out_u = (ub < bnd_u) ? ub : bnd_u;
    return make_float2(out_l, out_u);
}

__global__ void __launch_bounds__(32, 1) spu_transformer_kernel(
    const float4* __restrict__ bounds,       // (N/2) float4 = 2 rows each
    const float4* __restrict__ last_slopes,
    const float4* __restrict__ last_shifts,
    const float4* __restrict__ last_bounds,
    float4* __restrict__ out,
    int n4)                                   // number of float4 rows-pairs
{
    int i = blockIdx.x * blockDim.x + threadIdx.x;
    if (i >= n4) return;

    // All 4 loads issued back-to-back (MLP=4, 128B each per warp-lane group).
    float4 b   = bounds[i];
    float4 ls  = last_slopes[i];
    float4 lsh = last_shifts[i];
    float4 lb2 = last_bounds[i];

    float2 r0 = spu_row(make_float2(b.x, b.y),
                        make_float2(ls.x, ls.y),
                        make_float2(lsh.x, lsh.y),
                        make_float2(lb2.x, lb2.y));
    float2 r1 = spu_row(make_float2(b.z, b.w),
                        make_float2(ls.z, ls.w),
                        make_float2(lsh.z, lsh.w),
                        make_float2(lb2.z, lb2.w));

    out[i] = make_float4(r0.x, r0.y, r1.x, r1.y);
}

extern "C" void kernel_launch(void* const* d_in, const int* in_sizes, int n_in,
                              void* d_out, int out_size) {
    const float4* bounds      = (const float4*)d_in[0];
    const float4* last_slopes = (const float4*)d_in[1];
    const float4* last_shifts = (const float4*)d_in[2];
    const float4* last_bounds = (const float4*)d_in[3];
    float4* out = (float4*)d_out;

    int n4 = in_sizes[0] / 4;  // (N,2) floats -> N/2 float4 (2 rows per float4)
    int threads = 32;
    int blocks = (n4 + threads - 1) / threads;  // 4096/32 = 128 blocks
    spu_transformer_kernel<<<blocks, threads>>>(
        bounds, last_slopes, last_shifts, last_bounds, out, n4);
}

// round 3
// speedup vs baseline: 1.5035x; 1.5035x over previous
#include <cuda_runtime.h>

// SPU transformer bound propagation: elementwise over N=8192 rows.
// float4 = 2 rows per thread; 4096 threads total (32 blocks x 128).
// Fast-math sigmoid path (__expf + fast rcp): rel_err ~1e-6 << 1e-3 threshold.

__device__ __forceinline__ float spu_f(float x) {
    // x >= 0 : x*x - 0.5
    // x <  0 : 1/(1 + exp(x)) - 1
    float p = fmaf(x, x, -0.5f);
    float e = __expf(x);                  // FMUL + MUFU.EX2
    float n = __fdividef(1.0f, 1.0f + e) - 1.0f;  // MUFU.RCP path
    return (x >= 0.0f) ? p : n;
}

__device__ __forceinline__ float2 spu_row(float l, float u,
                                          float ls_l, float ls_u,
                                          float lsh_l, float lsh_u,
                                          float lb_l, float lb_u) {
    float vl = spu_f(l);
    float vu = spu_f(u);

    bool neg   = (u <= 0.0f);
    bool pos   = (l >= 0.0f);
    bool cross = !(neg || pos);

    float all_slopes = __fdividef(vu - vl, u - l);
    float slope_u = (pos || cross) ? all_slopes : 0.0f;
    float slope_l = neg ? all_slopes : 0.0f;

    bool sw = (all_slopes < 0.0f);
    float v_l = sw ? vu : vl;
    float v_u = sw ? vl : vu;
    float b_l = sw ? u : l;
    float b_u = sw ? l : u;

    float bnd_l = cross ? -0.5f : v_l;
    float bnd_u = v_u;

    float shift_u = fmaf(-slope_u, b_u, v_u);
    float shift_l = cross ? -0.5f : fmaf(-slope_l, b_l, v_l);

    float Ud = slope_u * ls_u;
    float UV = fmaf(slope_u, lsh_u, shift_u);
    float Ld = slope_l * ls_l;
    float LV = fmaf(slope_l, lsh_l, shift_l);

    float lb = fmaf(fmaxf(Ld, 0.0f), lb_l, fmaf(fminf(Ld, 0.0f), lb_u, LV));
    float ub = fmaf(fmaxf(Ud, 0.0f), lb_u, fmaf(fminf(Ud, 0.0f), lb_l, UV));

    return make_float2(fmaxf(lb, bnd_l), fminf(ub, bnd_u));
}

__global__ void __launch_bounds__(128, 1) spu_transformer_kernel(
    const float4* __restrict__ bounds,
    const float4* __restrict__ last_slopes,
    const float4* __restrict__ last_shifts,
    const float4* __restrict__ last_bounds,
    float4* __restrict__ out,
    int n4)
{
    int i = blockIdx.x * blockDim.x + threadIdx.x;
    if (i >= n4) return;

    float4 b   = bounds[i];
    float4 ls  = last_slopes[i];
    float4 lsh = last_shifts[i];
    float4 lb2 = last_bounds[i];

    float2 r0 = spu_row(b.x, b.y, ls.x, ls.y, lsh.x, lsh.y, lb2.x, lb2.y);
    float2 r1 = spu_row(b.z, b.w, ls.z, ls.w, lsh.z, lsh.w, lb2.z, lb2.w);

    out[i] = make_float4(r0.x, r0.y, r1.x, r1.y);
}

extern "C" void kernel_launch(void* const* d_in, const int* in_sizes, int n_in,
                              void* d_out, int out_size) {
    const float4* bounds      = (const float4*)d_in[0];
    const float4* last_slopes = (const float4*)d_in[1];
    const float4* last_shifts = (const float4*)d_in[2];
    const float4* last_bounds = (const float4*)d_in[3];
    float4* out = (float4*)d_out;

    int n4 = in_sizes[0] / 4;            // 8192*2 floats -> 4096 float4
    int threads = 128;
    int blocks = (n4 + threads - 1) / threads;   // 32 blocks
    spu_transformer_kernel<<<blocks, threads>>>(
        bounds, last_slopes, last_shifts, last_bounds, out, n4);
}